// round 4
// baseline (speedup 1.0000x reference)
#include <cuda_runtime.h>
#include <cstdint>

// NODE forest: B=1048576, 64 inputs, 8 trees x depth 6, TREE_DIM=2.
// R3: register-tile rebalance to j=8 samples/thread x P=6 selector-pairs
// (48 u64 accumulators). Shared-return bytes per FFMA2: 2.67 -> 1.67,
// making the fma pipe (not the LDS crossbar) the binding resource.
//
// Numerics (bit-faithful to reference):
//   z = fl(sequential ascending-i FMA dot) + b   (bias AFTER dot)
//   bit = fl(0.5 + 0.25*z) > 0.5                 (XLA logistic rounding)

#define THREADS 128
#define SPB 256
#define NBLK 4096

// ---- shared layout (bytes) ----
// Wp  : 24 rows x 66 u64 = 12672  @ 0
// bp  : 24 u64           = 192    @ 12672
// xs  : 256*64 f32       = 65536  @ 12864   (rotated float4 columns)
// tbl : 512 float2       = 4096   @ 78400
#define WP_STRIDE 66
#define XS_OFF   12864
#define TBL_OFF  78400
#define SMEM_BYTES 82496

static __device__ __forceinline__ unsigned long long pack2f(float lo, float hi) {
    unsigned long long r;
    asm("mov.b64 %0, {%1, %2};" : "=l"(r) : "f"(lo), "f"(hi));
    return r;
}
static __device__ __forceinline__ void unpack2f(unsigned long long v, float& lo, float& hi) {
    asm("mov.b64 {%0, %1}, %2;" : "=f"(lo), "=f"(hi) : "l"(v));
}
static __device__ __forceinline__ void ffma2(unsigned long long& d,
                                             unsigned long long a,
                                             unsigned long long b) {
    asm("fma.rn.f32x2 %0, %1, %2, %0;" : "+l"(d) : "l"(a), "l"(b));
}
static __device__ __forceinline__ void fadd2(unsigned long long& d,
                                             unsigned long long a) {
    asm("add.rn.f32x2 %0, %0, %1;" : "+l"(d) : "l"(a));
}
static __device__ __forceinline__ int xla_bit(float z) {
    return __fadd_rn(0.5f, __fmul_rn(0.25f, z)) > 0.5f;
}

__global__ __launch_bounds__(THREADS, 2)
void node_forest_kernel(const float*  __restrict__ x,      // [B,64]
                        const float*  __restrict__ Wsel,   // [48,64]
                        const float*  __restrict__ bsel,   // [48]
                        const float*  __restrict__ leafv,  // [8,64,2]
                        const float*  __restrict__ fcw,    // [2,16]
                        const float*  __restrict__ fcb,    // [2]
                        float2*       __restrict__ out)    // [B] float2
{
    extern __shared__ unsigned char smem[];
    unsigned long long* Wp  = (unsigned long long*)(smem);
    unsigned long long* bp  = (unsigned long long*)(smem + 12672);
    float*              xs  = (float*)(smem + XS_OFF);
    float2*             tbl = (float2*)(smem + TBL_OFF);

    const int tid  = threadIdx.x;
    const int base = blockIdx.x * SPB;

    // ---- stage x tile: float4, column rotated by (sample>>3) ----
    const float4* xg = (const float4*)x + (size_t)blockIdx.x * (SPB * 16);
    #pragma unroll
    for (int it = 0; it < 32; ++it) {
        int f = tid + it * THREADS;      // float4 index within tile (0..4095)
        float4 v = xg[f];
        int s = f >> 4;
        int c = f & 15;
        int slot = (c + (s >> 3)) & 15;
        *(float4*)(xs + s * 64 + slot * 4) = v;
    }

    // ---- pack W selector pairs, padded stride (66 u64) ----
    for (int e = tid; e < 1536; e += THREADS) {
        int P = e >> 6, i = e & 63;
        Wp[P * WP_STRIDE + i] = pack2f(Wsel[(2 * P) * 64 + i],
                                       Wsel[(2 * P + 1) * 64 + i]);
    }
    if (tid < 24) bp[tid] = pack2f(bsel[2 * tid], bsel[2 * tid + 1]);

    // ---- fold leaf_values with fc_w ----
    for (int e = tid; e < 512; e += THREADS) {
        int t = e >> 6, leaf = e & 63;
        float l0 = leafv[t * 128 + leaf * 2 + 0];
        float l1 = leafv[t * 128 + leaf * 2 + 1];
        tbl[e] = make_float2(l0 * fcw[t * 2]      + l1 * fcw[t * 2 + 1],
                             l0 * fcw[16 + t * 2] + l1 * fcw[16 + t * 2 + 1]);
    }
    __syncthreads();

    const int gq = tid & 3;     // selector group: trees 2gq, 2gq+1 (6 pairs)
    const int sg = tid >> 2;    // sample group: samples 8*sg .. 8*sg+7
    const int p0 = gq * 6;

    unsigned long long acc[6][8];
    #pragma unroll
    for (int p = 0; p < 6; ++p)
        #pragma unroll
        for (int j = 0; j < 8; ++j) acc[p][j] = 0ull;

    const float* xr = xs + sg * 8 * 64;   // 8 samples of 64 floats
    const unsigned long long* wbase = Wp + p0 * WP_STRIDE;

    // strictly ascending i per accumulator chain (order matches reference)
    #pragma unroll 2
    for (int i4 = 0; i4 < 16; ++i4) {
        const int i = i4 * 4;
        const int slot = ((i4 + sg) & 15) * 4;   // sample>>3 == sg for all 8 j

        // W for this i4: 6 pairs x 4 i-values (held across the 8 samples)
        ulonglong2 w01[6], w23[6];
        #pragma unroll
        for (int p = 0; p < 6; ++p) {
            w01[p] = *(const ulonglong2*)(wbase + p * WP_STRIDE + i);
            w23[p] = *(const ulonglong2*)(wbase + p * WP_STRIDE + i + 2);
        }

        #pragma unroll
        for (int j = 0; j < 8; ++j) {
            float4 v = *(const float4*)(xr + j * 64 + slot);
            unsigned long long d0 = pack2f(v.x, v.x);
            unsigned long long d1 = pack2f(v.y, v.y);
            unsigned long long d2 = pack2f(v.z, v.z);
            unsigned long long d3 = pack2f(v.w, v.w);
            #pragma unroll
            for (int p = 0; p < 6; ++p) {
                ffma2(acc[p][j], w01[p].x, d0);
                ffma2(acc[p][j], w01[p].y, d1);
                ffma2(acc[p][j], w23[p].x, d2);
                ffma2(acc[p][j], w23[p].y, d3);
            }
        }
    }

    // ---- bias (after dot), bits -> leaf idx -> folded-table gather ----
    #pragma unroll
    for (int p = 0; p < 6; ++p) {
        unsigned long long b2 = bp[p0 + p];
        #pragma unroll
        for (int j = 0; j < 8; ++j) fadd2(acc[p][j], b2);
    }

    const float fb0 = fcb[0], fb1 = fcb[1];
    float keepA0 = 0.f, keepA1 = 0.f, keepB0 = 0.f, keepB1 = 0.f;
    #pragma unroll
    for (int j = 0; j < 8; ++j) {
        int leafA = 0, leafB = 0;
        #pragma unroll
        for (int p = 0; p < 3; ++p) {
            float l, h;
            unpack2f(acc[p][j], l, h);
            if (xla_bit(l)) leafA |= (32 >> (2 * p));
            if (xla_bit(h)) leafA |= (16 >> (2 * p));
            unpack2f(acc[p + 3][j], l, h);
            if (xla_bit(l)) leafB |= (32 >> (2 * p));
            if (xla_bit(h)) leafB |= (16 >> (2 * p));
        }
        float2 ta = tbl[(2 * gq)     * 64 + leafA];
        float2 tb = tbl[(2 * gq + 1) * 64 + leafB];
        float s0 = ta.x + tb.x;
        float s1 = ta.y + tb.y;
        // reduce across the 4 gq lanes (consecutive lanes)
        s0 += __shfl_xor_sync(0xffffffffu, s0, 1);
        s1 += __shfl_xor_sync(0xffffffffu, s1, 1);
        s0 += __shfl_xor_sync(0xffffffffu, s0, 2);
        s1 += __shfl_xor_sync(0xffffffffu, s1, 2);
        if (j == gq)     { keepA0 = s0 + fb0; keepA1 = s1 + fb1; }
        if (j == gq + 4) { keepB0 = s0 + fb0; keepB1 = s1 + fb1; }
    }
    // lane (sg,gq) stores samples 8*sg+gq and 8*sg+4+gq
    out[base + sg * 8 + gq]     = make_float2(keepA0, keepA1);
    out[base + sg * 8 + 4 + gq] = make_float2(keepB0, keepB1);
}

extern "C" void kernel_launch(void* const* d_in, const int* in_sizes, int n_in,
                              void* d_out, int out_size) {
    (void)in_sizes; (void)n_in; (void)out_size;
    cudaFuncSetAttribute(node_forest_kernel,
                         cudaFuncAttributeMaxDynamicSharedMemorySize, SMEM_BYTES);
    node_forest_kernel<<<NBLK, THREADS, SMEM_BYTES>>>(
        (const float*)d_in[0],   // x
        (const float*)d_in[1],   // W_sel
        (const float*)d_in[2],   // b_sel
        (const float*)d_in[3],   // leaf_values
        (const float*)d_in[4],   // fc_w
        (const float*)d_in[5],   // fc_b
        (float2*)d_out);
}